// round 9
// baseline (speedup 1.0000x reference)
#include <cuda_runtime.h>
#include <cstdint>

// ---------------------------------------------------------------------------
// Problem constants
// ---------------------------------------------------------------------------
#define K_CODES 1024
#define C_DIM   256
#define HW      4096
#define BATCH   32
#define NPIX    (BATCH*HW)          // 131072
#define QN      (BATCH*C_DIM*HW)    // 8388608

#define TNPIX   64                  // pixels per CTA
#define MARGIN  2.5e-2f             // covers int8 quantization error bound (~1.4e-2)
#define SLOTS   24                  // candidate slots per pixel (+ exact fallback)

// Scratch (device globals; no cudaMalloc allowed)
__device__ float g_enorm[K_CODES];
__device__ float g_xnorm[NPIX];
__device__ float g_xc1[NPIX];       // 2*maxabs/(127*130048) per pixel
__device__ int   g_idx[NPIX];
__device__ __align__(16) signed char g_cbi8[K_CODES * C_DIM];
__device__ __align__(16) signed char g_xi8[(size_t)NPIX * C_DIM];  // pixel-major

// ---------------------------------------------------------------------------
// PTX helpers — plain features only (compute_103-safe)
// ---------------------------------------------------------------------------
#define MMA_S8(d, a0, a1, a2, a3, b0, b1) \
    asm volatile("mma.sync.aligned.m16n8k32.row.col.s32.s8.s8.s32 " \
        "{%0,%1,%2,%3}, {%4,%5,%6,%7}, {%8,%9}, {%0,%1,%2,%3};" \
        : "+r"((d)[0]), "+r"((d)[1]), "+r"((d)[2]), "+r"((d)[3]) \
        : "r"(a0), "r"(a1), "r"(a2), "r"(a3), "r"(b0), "r"(b1))
#define CP_ASYNC16(dst, src) \
    asm volatile("cp.async.cg.shared.global [%0], [%1], 16;" :: "r"(dst), "l"(src))
#define CP_COMMIT() asm volatile("cp.async.commit_group;")
#define CP_WAIT0()  asm volatile("cp.async.wait_group 0;")

__device__ __forceinline__ uint32_t smem_u32(const void* p) {
    uint32_t a;
    asm("{ .reg .u64 t; cvta.to.shared.u64 t, %1; cvt.u32.u64 %0, t; }" : "=r"(a) : "l"(p));
    return a;
}
__device__ __forceinline__ unsigned long long packkey(float s, int k) {
    unsigned u = __float_as_uint(s);
    u = (u & 0x80000000u) ? ~u : (u | 0x80000000u);
    return ((unsigned long long)u << 32) | (unsigned)k;
}
__device__ __forceinline__ float unpack_score(unsigned long long key) {
    unsigned u = (unsigned)(key >> 32);
    u = (u & 0x80000000u) ? (u & 0x7FFFFFFFu) : ~u;
    return __uint_as_float(u);
}

// ---------------------------------------------------------------------------
// 1) fused prep kernel (single launch):
//    blocks [0,1024):    cb -> int8 (scale 1024*127)
//    blocks [1024,1028):  codebook row norms (exact, unchanged semantics)
//    blocks [1028,1540):  per-pixel: maxabs -> scale, exact xnorm, x -> int8
// ---------------------------------------------------------------------------
__global__ void prep_kernel(const float* __restrict__ x, const float* __restrict__ cb) {
    const int bid = blockIdx.x, tid = threadIdx.x;
    if (bid < 1024) {
        int f = bid * 256 + tid;
        float v = cb[f];
        int q = __float2int_rn(v * 130048.0f);
        q = max(-127, min(127, q));
        g_cbi8[f] = (signed char)q;
    } else if (bid < 1028) {
        int k = (bid - 1024) * 256 + tid;
        const float4* row = reinterpret_cast<const float4*>(cb + (size_t)k * C_DIM);
        float s = 0.f;
        #pragma unroll
        for (int i = 0; i < C_DIM / 4; i++) {
            float4 v = row[i];
            s += v.x*v.x + v.y*v.y + v.z*v.z + v.w*v.w;
        }
        g_enorm[k] = s;
    } else {
        int p = (bid - 1028) * 256 + tid;
        int b  = p >> 12;
        int hw = p & (HW - 1);
        const float* xb = x + (size_t)b * C_DIM * HW + hw;
        // pass 1: maxabs
        float maxa = 0.f;
        #pragma unroll 8
        for (int c = 0; c < C_DIM; c++) {
            float v = fabsf(xb[(size_t)c * HW]);
            if (v > maxa) maxa = v;
        }
        maxa = fmaxf(maxa, 1e-20f);
        float scale = 127.0f / maxa;
        // pass 2: exact xnorm (reference order) + int8 quantization
        float s = 0.f;
        uint32_t* out = reinterpret_cast<uint32_t*>(&g_xi8[(size_t)p * C_DIM]);
        #pragma unroll 4
        for (int c4 = 0; c4 < C_DIM / 4; c4++) {
            uint32_t pk = 0;
            #pragma unroll
            for (int j = 0; j < 4; j++) {
                float v = xb[(size_t)(c4 * 4 + j) * HW];
                s = __fadd_rn(s, __fmul_rn(v, v));
                int q = __float2int_rn(v * scale);
                q = max(-127, min(127, q));
                pk |= ((uint32_t)(q & 0xFF)) << (j * 8);
            }
            out[c4] = pk;
        }
        g_xnorm[p] = s;
        g_xc1[p] = 2.0f * maxa / (127.0f * 130048.0f);
    }
}

// ---------------------------------------------------------------------------
// 2) fused VQ kernel: 64 px/CTA x 1024 codes, int8 m16n8k32 MMA (exact int dot),
//    running-min + margin candidate emission -> exact fp32-chain recheck.
//    Warp tile: 64 codes x 32 px (8 warps = 4 code-groups x 2 px-groups).
//    2 CTAs/SM (smem ~54KB, regs <= 128).
// ---------------------------------------------------------------------------
#define XB_STRIDE 272              // bytes per px row (256 data + 16 pad), conflict-free
#define CB_ROW    48               // bytes per code row per 32-c chunk, conflict-free
#define CB_BUF    12288            // 256 rows * 48
#define OFF_XB    0                // 64*272 = 17408
#define OFF_CB    17408            // 2*12288 = 24576
#define OFF_EN    41984            // 4096
#define OFF_XN    46080            // 256
#define OFF_XC1   46336            // 256
#define OFF_BEST  46592            // 512
#define OFF_BESTE 47104            // 512
#define OFF_CNTPX 47616            // 256
#define OFF_CAND  47872            // 64*24*4 = 6144
#define SMEM_TOTAL 54016

__global__ __launch_bounds__(256, 2)
void vq_mma_kernel(const float* __restrict__ x, const float* __restrict__ cb) {
    extern __shared__ char smem[];
    const uint32_t sb = smem_u32(smem);
    const int tid = threadIdx.x, wid = tid >> 5, lane = tid & 31;
    const int wc = wid >> 1;            // code group (0..3): 64 codes
    const int wp = wid & 1;             // pixel group (0..1): 32 px
    const int p0 = blockIdx.x * TNPIX;
    const int bb = p0 >> 12;
    const int hw0 = p0 & (HW - 1);

    float* en_s  = reinterpret_cast<float*>(smem + OFF_EN);
    float* xn_s  = reinterpret_cast<float*>(smem + OFF_XN);
    float* xc1_s = reinterpret_cast<float*>(smem + OFF_XC1);
    unsigned long long* best  = reinterpret_cast<unsigned long long*>(smem + OFF_BEST);
    unsigned long long* beste = reinterpret_cast<unsigned long long*>(smem + OFF_BESTE);
    int* cnt_px = reinterpret_cast<int*>(smem + OFF_CNTPX);
    unsigned* cand = reinterpret_cast<unsigned*>(smem + OFF_CAND);

    // prefetch CB chunk 0 (256 codes x 32 c)
    {
        uint32_t dbase = sb + OFF_CB;
        const signed char* src0 = g_cbi8;
        #pragma unroll
        for (int i = 0; i < 2; i++) {
            int f = tid + i * 256;        // 0..511
            int row = f >> 1, seg = f & 1;
            CP_ASYNC16(dbase + row * CB_ROW + seg * 16,
                       src0 + (size_t)row * 256 + seg * 16);
        }
        CP_COMMIT();
    }

    if (tid < TNPIX) {
        xn_s[tid]  = g_xnorm[p0 + tid];
        xc1_s[tid] = g_xc1[p0 + tid];
        best[tid]  = 0xFFFFFFFFFFFFFFFFULL;
        beste[tid] = 0xFFFFFFFFFFFFFFFFULL;
        cnt_px[tid] = 0;
    }
    for (int i = tid; i < K_CODES; i += 256) en_s[i] = g_enorm[i];

    // XB tile: 64 px x 256 c int8, pixel-major (coalesced 16B loads)
    {
        const signed char* src = &g_xi8[(size_t)p0 * C_DIM];
        #pragma unroll
        for (int i = 0; i < 4; i++) {
            int f = tid + i * 256;        // 0..1023 16B units
            int px = f >> 4, u = f & 15;
            uint4 v = *reinterpret_cast<const uint4*>(src + (size_t)px * 256 + u * 16);
            *reinterpret_cast<uint4*>(smem + OFF_XB + px * XB_STRIDE + u * 16) = v;
        }
    }

    int acc[4][4][4];

    // 32 chunk-steps: kt = g>>3 (256-code stage), cc = g&7 (32-c slice)
    for (int g = 0; g < 32; g++) {
        const int buf = g & 1;
        CP_WAIT0();
        __syncthreads();   // chunk g visible; all warps done reading buf^1 (iter g-1)

        if (g < 31) {       // prefetch chunk g+1 into other buffer
            int gn = g + 1;
            int ktn = gn >> 3, ccn = gn & 7;
            uint32_t dbase = sb + OFF_CB + (buf ^ 1) * CB_BUF;
            const signed char* srcb = g_cbi8 + (size_t)(ktn * 256) * 256 + ccn * 32;
            #pragma unroll
            for (int i = 0; i < 2; i++) {
                int f = tid + i * 256;
                int row = f >> 1, seg = f & 1;
                CP_ASYNC16(dbase + row * CB_ROW + seg * 16,
                           srcb + (size_t)row * 256 + seg * 16);
            }
            CP_COMMIT();
        }

        const int cc = g & 7;
        if (cc == 0) {
            #pragma unroll
            for (int m = 0; m < 4; m++)
                #pragma unroll
                for (int n = 0; n < 4; n++)
                    #pragma unroll
                    for (int j = 0; j < 4; j++) acc[m][n][j] = 0;
        }

        // B fragments (x): col-major px, k contiguous
        uint32_t bf0[4], bf1[4];
        {
            const char* xbase = smem + OFF_XB + cc * 32 + (lane & 3) * 4;
            #pragma unroll
            for (int n = 0; n < 4; n++) {
                const char* a = xbase + (wp * 32 + n * 8 + (lane >> 2)) * XB_STRIDE;
                bf0[n] = *reinterpret_cast<const uint32_t*>(a);
                bf1[n] = *reinterpret_cast<const uint32_t*>(a + 16);
            }
        }
        // A fragments (cb) + MMA
        {
            const char* abase = smem + OFF_CB + buf * CB_BUF + (lane & 3) * 4;
            #pragma unroll
            for (int m = 0; m < 4; m++) {
                const char* a = abase + (wc * 64 + m * 16 + (lane >> 2)) * CB_ROW;
                uint32_t a0 = *reinterpret_cast<const uint32_t*>(a);
                uint32_t a1 = *reinterpret_cast<const uint32_t*>(a + 8 * CB_ROW);
                uint32_t a2 = *reinterpret_cast<const uint32_t*>(a + 16);
                uint32_t a3 = *reinterpret_cast<const uint32_t*>(a + 8 * CB_ROW + 16);
                #pragma unroll
                for (int n = 0; n < 4; n++)
                    MMA_S8(acc[m][n], a0, a1, a2, a3, bf0[n], bf1[n]);
            }
        }

        if (cc == 7) {   // stage epilogue: 256 codes scored
            const int kt = g >> 3;
            // running-min: thread min -> reduce over code-rows (lane>>2) -> atomicMin
            #pragma unroll
            for (int n = 0; n < 4; n++)
                #pragma unroll
                for (int co = 0; co < 2; co++) {
                    int px = wp * 32 + n * 8 + (lane & 3) * 2 + co;
                    float xn = xn_s[px], c1 = xc1_s[px];
                    unsigned long long kk = 0xFFFFFFFFFFFFFFFFULL;
                    #pragma unroll
                    for (int m = 0; m < 4; m++)
                        #pragma unroll
                        for (int rr = 0; rr < 2; rr++) {
                            int code = kt * 256 + wc * 64 + m * 16 + (lane >> 2) + rr * 8;
                            float s = __fsub_rn(__fadd_rn(xn, en_s[code]),
                                                __fmul_rn((float)acc[m][n][rr * 2 + co], c1));
                            unsigned long long k2 = packkey(s, code);
                            if (k2 < kk) kk = k2;
                        }
                    #pragma unroll
                    for (int d = 4; d < 32; d <<= 1) {
                        unsigned long long o = __shfl_xor_sync(0xFFFFFFFFu, kk, d);
                        if (o < kk) kk = o;
                    }
                    if ((lane >> 2) == 0) atomicMin(&best[px], kk);
                }
            __syncthreads();
            // candidate emission vs running min (superset of final winners)
            #pragma unroll
            for (int n = 0; n < 4; n++)
                #pragma unroll
                for (int co = 0; co < 2; co++) {
                    int px = wp * 32 + n * 8 + (lane & 3) * 2 + co;
                    float thr = unpack_score(best[px]) + MARGIN;
                    float xn = xn_s[px], c1 = xc1_s[px];
                    #pragma unroll
                    for (int m = 0; m < 4; m++)
                        #pragma unroll
                        for (int rr = 0; rr < 2; rr++) {
                            int code = kt * 256 + wc * 64 + m * 16 + (lane >> 2) + rr * 8;
                            float s = __fsub_rn(__fadd_rn(xn, en_s[code]),
                                                __fmul_rn((float)acc[m][n][rr * 2 + co], c1));
                            if (s <= thr) {
                                int slot = atomicAdd(&cnt_px[px], 1);
                                if (slot < SLOTS) cand[px * SLOTS + slot] = (unsigned)code;
                            }
                        }
                }
        }
    }
    __syncthreads();

    // ---- exact recheck: sequential fp32 FMA chain, c ascending (reference order)
    for (int idx = tid; idx < TNPIX * SLOTS; idx += 256) {
        int px = idx / SLOTS, sl = idx - px * SLOTS;
        int nc = cnt_px[px]; if (nc > SLOTS) nc = SLOTS;
        if (sl < nc) {
            int k = (int)cand[idx];
            const float* xp = x + (size_t)bb * C_DIM * HW + (hw0 + px);
            const float* ck = cb + (size_t)k * C_DIM;
            float dot = 0.f;
            #pragma unroll 8
            for (int c = 0; c < C_DIM; c++)
                dot = __fmaf_rn(ck[c], xp[(size_t)c * HW], dot);
            float s = __fsub_rn(__fadd_rn(xn_s[px], en_s[k]), __fmul_rn(2.f, dot));
            atomicMin(&beste[px], packkey(s, k));
        }
    }
    __syncthreads();
    // overflow fallback (provably safe, ~never taken): full exact scan for that pixel
    for (int px = 0; px < TNPIX; px++) {
        if (cnt_px[px] > SLOTS) {
            const float* xp = x + (size_t)bb * C_DIM * HW + (hw0 + px);
            for (int k = tid; k < K_CODES; k += 256) {
                const float* ck = cb + (size_t)k * C_DIM;
                float dot = 0.f;
                #pragma unroll 8
                for (int c = 0; c < C_DIM; c++)
                    dot = __fmaf_rn(ck[c], xp[(size_t)c * HW], dot);
                float s = __fsub_rn(__fadd_rn(xn_s[px], en_s[k]), __fmul_rn(2.f, dot));
                atomicMin(&beste[px], packkey(s, k));
            }
        }
    }
    __syncthreads();
    if (tid < TNPIX) g_idx[p0 + tid] = (int)(beste[tid] & 0xFFFFFFFFu);
}

// ---------------------------------------------------------------------------
// 3) outputs (unchanged)
// ---------------------------------------------------------------------------
__global__ void gather_kernel(const float* __restrict__ cb, float* __restrict__ q) {
    long long o = (long long)blockIdx.x * blockDim.x + threadIdx.x;
    if (o >= (long long)QN) return;
    int hw = (int)(o & (HW - 1));
    long long t = o >> 12;
    int c = (int)(t & (C_DIM - 1));
    int b = (int)(t >> 8);
    int k = g_idx[b * HW + hw];
    q[o] = __ldg(cb + (size_t)k * C_DIM + c);
}
__global__ void idxf_kernel(float* __restrict__ out) {
    int n = blockIdx.x * blockDim.x + threadIdx.x;
    if (n < NPIX) out[n] = (float)g_idx[n];
}
__global__ void idxi_kernel(int* __restrict__ out) {
    int n = blockIdx.x * blockDim.x + threadIdx.x;
    if (n < NPIX) out[n] = g_idx[n];
}

// ---------------------------------------------------------------------------
extern "C" void kernel_launch(void* const* d_in, const int* in_sizes, int n_in,
                              void* d_out, int out_size) {
    const float* x  = (const float*)d_in[0];   // (32,256,64,64) f32
    const float* cb = (const float*)d_in[1];   // (1024,256) f32

    cudaFuncSetAttribute(vq_mma_kernel,
                         cudaFuncAttributeMaxDynamicSharedMemorySize, SMEM_TOTAL);

    prep_kernel<<<1540, 256>>>(x, cb);
    vq_mma_kernel<<<NPIX / TNPIX, 256, SMEM_TOTAL>>>(x, cb);

    if (out_size >= NPIX + QN) {
        idxf_kernel<<<NPIX / 256, 256>>>((float*)d_out);
        gather_kernel<<<QN / 256, 256>>>(cb, (float*)d_out + NPIX);
    } else if (out_size >= QN) {
        gather_kernel<<<QN / 256, 256>>>(cb, (float*)d_out);
    } else if (out_size >= NPIX) {
        idxi_kernel<<<NPIX / 256, 256>>>((int*)d_out);
    }
}

// round 11
// speedup vs baseline: 52.0795x; 52.0795x over previous
#include <cuda_runtime.h>
#include <cstdint>

// ---------------------------------------------------------------------------
// Problem constants
// ---------------------------------------------------------------------------
#define K_CODES 1024
#define C_DIM   256
#define HW      4096
#define BATCH   32
#define NPIX    (BATCH*HW)          // 131072
#define QN      (BATCH*C_DIM*HW)    // 8388608

#define TNPIX   64                  // pixels per CTA
#define SLOTS   64                  // candidate slots per pixel (+ exact fallback)
#define QE      3.8448e-6f          // 0.5/130048 cb quantization step/2

// Scratch (device globals; no cudaMalloc allowed)
__device__ float g_enorm[K_CODES];
__device__ float g_en1[K_CODES];    // sum |e| per code
__device__ float g_xnorm[NPIX];
__device__ float g_xn1[NPIX];       // sum |x| per pixel
__device__ float g_xc1[NPIX];       // 2*maxa/(127*130048) per pixel
__device__ int   g_idx[NPIX];
__device__ __align__(16) signed char g_cbi8[K_CODES * C_DIM];
__device__ __align__(16) signed char g_xi8[(size_t)NPIX * C_DIM];  // pixel-major

// ---------------------------------------------------------------------------
// PTX helpers — plain features only (compute_103-safe)
// ---------------------------------------------------------------------------
#define MMA_S8(d, a0, a1, a2, a3, b0, b1) \
    asm volatile("mma.sync.aligned.m16n8k32.row.col.s32.s8.s8.s32 " \
        "{%0,%1,%2,%3}, {%4,%5,%6,%7}, {%8,%9}, {%0,%1,%2,%3};" \
        : "+r"((d)[0]), "+r"((d)[1]), "+r"((d)[2]), "+r"((d)[3]) \
        : "r"(a0), "r"(a1), "r"(a2), "r"(a3), "r"(b0), "r"(b1))
#define CP_ASYNC16(dst, src) \
    asm volatile("cp.async.cg.shared.global [%0], [%1], 16;" :: "r"(dst), "l"(src))
#define CP_COMMIT() asm volatile("cp.async.commit_group;")
#define CP_WAIT0()  asm volatile("cp.async.wait_group 0;")

__device__ __forceinline__ uint32_t smem_u32(const void* p) {
    uint32_t a;
    asm("{ .reg .u64 t; cvta.to.shared.u64 t, %1; cvt.u32.u64 %0, t; }" : "=r"(a) : "l"(p));
    return a;
}
__device__ __forceinline__ unsigned long long packkey(float s, int k) {
    unsigned u = __float_as_uint(s);
    u = (u & 0x80000000u) ? ~u : (u | 0x80000000u);
    return ((unsigned long long)u << 32) | (unsigned)k;
}
__device__ __forceinline__ float unpack_score(unsigned long long key) {
    unsigned u = (unsigned)(key >> 32);
    u = (u & 0x80000000u) ? (u & 0x7FFFFFFFu) : ~u;
    return __uint_as_float(u);
}

// ---------------------------------------------------------------------------
// 1) fused prep kernel:
//    blocks [0,1024):     cb -> int8 (scale 1024*127)
//    blocks [1024,1028):  codebook row norms (exact) + row 1-norms
//    blocks [1028,1540):  per-pixel: maxabs+1-norm -> scale, exact xnorm, x->int8
// ---------------------------------------------------------------------------
__global__ void prep_kernel(const float* __restrict__ x, const float* __restrict__ cb) {
    const int bid = blockIdx.x, tid = threadIdx.x;
    if (bid < 1024) {
        int f = bid * 256 + tid;
        float v = cb[f];
        int q = __float2int_rn(v * 130048.0f);
        q = max(-127, min(127, q));
        g_cbi8[f] = (signed char)q;
    } else if (bid < 1028) {
        int k = (bid - 1024) * 256 + tid;
        const float4* row = reinterpret_cast<const float4*>(cb + (size_t)k * C_DIM);
        float s = 0.f, s1 = 0.f;
        #pragma unroll
        for (int i = 0; i < C_DIM / 4; i++) {
            float4 v = row[i];
            s  += v.x*v.x + v.y*v.y + v.z*v.z + v.w*v.w;
            s1 += fabsf(v.x) + fabsf(v.y) + fabsf(v.z) + fabsf(v.w);
        }
        g_enorm[k] = s;
        g_en1[k] = s1;
    } else {
        int p = (bid - 1028) * 256 + tid;
        int b  = p >> 12;
        int hw = p & (HW - 1);
        const float* xb = x + (size_t)b * C_DIM * HW + hw;
        // pass 1: maxabs + 1-norm
        float maxa = 0.f, s1 = 0.f;
        #pragma unroll 8
        for (int c = 0; c < C_DIM; c++) {
            float v = fabsf(xb[(size_t)c * HW]);
            s1 += v;
            if (v > maxa) maxa = v;
        }
        maxa = fmaxf(maxa, 1e-20f);
        float scale = 127.0f / maxa;
        // pass 2: exact xnorm (reference order) + int8 quantization
        float s = 0.f;
        uint32_t* out = reinterpret_cast<uint32_t*>(&g_xi8[(size_t)p * C_DIM]);
        #pragma unroll 4
        for (int c4 = 0; c4 < C_DIM / 4; c4++) {
            uint32_t pk = 0;
            #pragma unroll
            for (int j = 0; j < 4; j++) {
                float v = xb[(size_t)(c4 * 4 + j) * HW];
                s = __fadd_rn(s, __fmul_rn(v, v));
                int q = __float2int_rn(v * scale);
                q = max(-127, min(127, q));
                pk |= ((uint32_t)(q & 0xFF)) << (j * 8);
            }
            out[c4] = pk;
        }
        g_xnorm[p] = s;
        g_xn1[p] = s1;
        g_xc1[p] = 2.0f * maxa / (127.0f * 130048.0f);
    }
}

// ---------------------------------------------------------------------------
// 2) fused VQ kernel: int8 m16n8k32 MMA + per-pixel PROVABLE margin emission
//    + exact fp32-chain recheck (reference bit-semantics). 2 CTAs/SM.
// ---------------------------------------------------------------------------
#define XB_STRIDE 272
#define CB_ROW    48
#define CB_BUF    12288            // 256 rows * 48
#define OFF_XB    0                // 17408
#define OFF_CB    17408            // 24576
#define OFF_EN    41984            // 4096
#define OFF_XN    46080            // 256
#define OFF_C1    46336            // 256
#define OFF_MG    46592            // 256
#define OFF_BEST  46848            // 512
#define OFF_BESTE 47360            // 512
#define OFF_CNTPX 47872            // 256
#define OFF_RED   48128            // 64
#define OFF_CAND  48192            // 64*64*4 = 16384
#define SMEM_TOTAL 64576

__global__ __launch_bounds__(256, 2)
void vq_mma_kernel(const float* __restrict__ x, const float* __restrict__ cb) {
    extern __shared__ char smem[];
    const uint32_t sb = smem_u32(smem);
    const int tid = threadIdx.x, wid = tid >> 5, lane = tid & 31;
    const int wc = wid >> 1;            // code group (0..3): 64 codes
    const int wp = wid & 1;             // pixel group (0..1): 32 px
    const int p0 = blockIdx.x * TNPIX;
    const int bb = p0 >> 12;
    const int hw0 = p0 & (HW - 1);

    float* en_s  = reinterpret_cast<float*>(smem + OFF_EN);
    float* xn_s  = reinterpret_cast<float*>(smem + OFF_XN);
    float* c1_s  = reinterpret_cast<float*>(smem + OFF_C1);
    float* mg_s  = reinterpret_cast<float*>(smem + OFF_MG);
    float* red_s = reinterpret_cast<float*>(smem + OFF_RED);
    unsigned long long* best  = reinterpret_cast<unsigned long long*>(smem + OFF_BEST);
    unsigned long long* beste = reinterpret_cast<unsigned long long*>(smem + OFF_BESTE);
    int* cnt_px = reinterpret_cast<int*>(smem + OFF_CNTPX);
    unsigned* cand = reinterpret_cast<unsigned*>(smem + OFF_CAND);

    // prefetch CB chunk 0 (256 codes x 32 c)
    {
        uint32_t dbase = sb + OFF_CB;
        const signed char* src0 = g_cbi8;
        #pragma unroll
        for (int i = 0; i < 2; i++) {
            int f = tid + i * 256;
            int row = f >> 1, seg = f & 1;
            CP_ASYNC16(dbase + row * CB_ROW + seg * 16,
                       src0 + (size_t)row * 256 + seg * 16);
        }
        CP_COMMIT();
    }

    float xn1 = 0.f;
    if (tid < TNPIX) {
        xn_s[tid] = g_xnorm[p0 + tid];
        c1_s[tid] = g_xc1[p0 + tid];
        xn1       = g_xn1[p0 + tid];
        best[tid]  = 0xFFFFFFFFFFFFFFFFULL;
        beste[tid] = 0xFFFFFFFFFFFFFFFFULL;
        cnt_px[tid] = 0;
    }
    for (int i = tid; i < K_CODES; i += 256) en_s[i] = g_enorm[i];

    // EN1MAX block reduction (max over 1024 code 1-norms)
    {
        float m = 0.f;
        #pragma unroll
        for (int j = 0; j < 4; j++) m = fmaxf(m, g_en1[tid * 4 + j]);
        #pragma unroll
        for (int d = 16; d > 0; d >>= 1)
            m = fmaxf(m, __shfl_xor_sync(0xFFFFFFFFu, m, d));
        if (lane == 0) red_s[wid] = m;
    }
    __syncthreads();
    {
        float en1max = red_s[0];
        #pragma unroll
        for (int w = 1; w < 8; w++) en1max = fmaxf(en1max, red_s[w]);
        if (tid < TNPIX) {
            // qx = maxa/254 = c1 * 130048/4
            float qx = c1_s[tid] * 32512.0f;
            // margin = 2 * eps_max, eps = 2*qx*EN1MAX + 2*QE*xn1 + slack
            mg_s[tid] = 2.0f * (2.0f * qx * en1max + 2.0f * QE * xn1 + 5e-4f);
        }
    }

    // XB tile: 64 px x 256 c int8, pixel-major
    {
        const signed char* src = &g_xi8[(size_t)p0 * C_DIM];
        #pragma unroll
        for (int i = 0; i < 4; i++) {
            int f = tid + i * 256;
            int px = f >> 4, u = f & 15;
            uint4 v = *reinterpret_cast<const uint4*>(src + (size_t)px * 256 + u * 16);
            *reinterpret_cast<uint4*>(smem + OFF_XB + px * XB_STRIDE + u * 16) = v;
        }
    }

    int acc[4][4][4];

    // 32 chunk-steps: kt = g>>3 (256-code stage), cc = g&7 (32-c slice)
    for (int g = 0; g < 32; g++) {
        const int buf = g & 1;
        CP_WAIT0();
        __syncthreads();

        if (g < 31) {
            int gn = g + 1;
            int ktn = gn >> 3, ccn = gn & 7;
            uint32_t dbase = sb + OFF_CB + (buf ^ 1) * CB_BUF;
            const signed char* srcb = g_cbi8 + (size_t)(ktn * 256) * 256 + ccn * 32;
            #pragma unroll
            for (int i = 0; i < 2; i++) {
                int f = tid + i * 256;
                int row = f >> 1, seg = f & 1;
                CP_ASYNC16(dbase + row * CB_ROW + seg * 16,
                           srcb + (size_t)row * 256 + seg * 16);
            }
            CP_COMMIT();
        }

        const int cc = g & 7;
        if (cc == 0) {
            #pragma unroll
            for (int m = 0; m < 4; m++)
                #pragma unroll
                for (int n = 0; n < 4; n++)
                    #pragma unroll
                    for (int j = 0; j < 4; j++) acc[m][n][j] = 0;
        }

        uint32_t bf0[4], bf1[4];
        {
            const char* xbase = smem + OFF_XB + cc * 32 + (lane & 3) * 4;
            #pragma unroll
            for (int n = 0; n < 4; n++) {
                const char* a = xbase + (wp * 32 + n * 8 + (lane >> 2)) * XB_STRIDE;
                bf0[n] = *reinterpret_cast<const uint32_t*>(a);
                bf1[n] = *reinterpret_cast<const uint32_t*>(a + 16);
            }
        }
        {
            const char* abase = smem + OFF_CB + buf * CB_BUF + (lane & 3) * 4;
            #pragma unroll
            for (int m = 0; m < 4; m++) {
                const char* a = abase + (wc * 64 + m * 16 + (lane >> 2)) * CB_ROW;
                uint32_t a0 = *reinterpret_cast<const uint32_t*>(a);
                uint32_t a1 = *reinterpret_cast<const uint32_t*>(a + 8 * CB_ROW);
                uint32_t a2 = *reinterpret_cast<const uint32_t*>(a + 16);
                uint32_t a3 = *reinterpret_cast<const uint32_t*>(a + 8 * CB_ROW + 16);
                #pragma unroll
                for (int n = 0; n < 4; n++)
                    MMA_S8(acc[m][n], a0, a1, a2, a3, bf0[n], bf1[n]);
            }
        }

        if (cc == 7) {   // stage epilogue: 256 codes scored
            const int kt = g >> 3;
            #pragma unroll
            for (int n = 0; n < 4; n++)
                #pragma unroll
                for (int co = 0; co < 2; co++) {
                    int px = wp * 32 + n * 8 + (lane & 3) * 2 + co;
                    float xn = xn_s[px], c1 = c1_s[px];
                    unsigned long long kk = 0xFFFFFFFFFFFFFFFFULL;
                    #pragma unroll
                    for (int m = 0; m < 4; m++)
                        #pragma unroll
                        for (int rr = 0; rr < 2; rr++) {
                            int code = kt * 256 + wc * 64 + m * 16 + (lane >> 2) + rr * 8;
                            float s = __fsub_rn(__fadd_rn(xn, en_s[code]),
                                                __fmul_rn((float)acc[m][n][rr * 2 + co], c1));
                            unsigned long long k2 = packkey(s, code);
                            if (k2 < kk) kk = k2;
                        }
                    #pragma unroll
                    for (int d = 4; d < 32; d <<= 1) {
                        unsigned long long o = __shfl_xor_sync(0xFFFFFFFFu, kk, d);
                        if (o < kk) kk = o;
                    }
                    if ((lane >> 2) == 0) atomicMin(&best[px], kk);
                }
            __syncthreads();
            // candidate emission vs running min + provable per-pixel margin
            #pragma unroll
            for (int n = 0; n < 4; n++)
                #pragma unroll
                for (int co = 0; co < 2; co++) {
                    int px = wp * 32 + n * 8 + (lane & 3) * 2 + co;
                    float thr = unpack_score(best[px]) + mg_s[px];
                    float xn = xn_s[px], c1 = c1_s[px];
                    #pragma unroll
                    for (int m = 0; m < 4; m++)
                        #pragma unroll
                        for (int rr = 0; rr < 2; rr++) {
                            int code = kt * 256 + wc * 64 + m * 16 + (lane >> 2) + rr * 8;
                            float s = __fsub_rn(__fadd_rn(xn, en_s[code]),
                                                __fmul_rn((float)acc[m][n][rr * 2 + co], c1));
                            if (s <= thr) {
                                int slot = atomicAdd(&cnt_px[px], 1);
                                if (slot < SLOTS) cand[px * SLOTS + slot] = (unsigned)code;
                            }
                        }
                }
        }
    }
    __syncthreads();

    // ---- exact recheck: sequential fp32 FMA chain, c ascending (reference order)
    for (int idx = tid; idx < TNPIX * SLOTS; idx += 256) {
        int px = idx >> 6, sl = idx & (SLOTS - 1);
        int nc = cnt_px[px]; if (nc > SLOTS) nc = SLOTS;
        if (sl < nc) {
            int k = (int)cand[idx];
            const float* xp = x + (size_t)bb * C_DIM * HW + (hw0 + px);
            const float* ck = cb + (size_t)k * C_DIM;
            float dot = 0.f;
            #pragma unroll 8
            for (int c = 0; c < C_DIM; c++)
                dot = __fmaf_rn(ck[c], xp[(size_t)c * HW], dot);
            float s = __fsub_rn(__fadd_rn(xn_s[px], en_s[k]), __fmul_rn(2.f, dot));
            atomicMin(&beste[px], packkey(s, k));
        }
    }
    __syncthreads();
    // overflow fallback (provably safe; ~never taken with SLOTS=64)
    for (int px = 0; px < TNPIX; px++) {
        if (cnt_px[px] > SLOTS) {
            const float* xp = x + (size_t)bb * C_DIM * HW + (hw0 + px);
            for (int k = tid; k < K_CODES; k += 256) {
                const float* ck = cb + (size_t)k * C_DIM;
                float dot = 0.f;
                #pragma unroll 8
                for (int c = 0; c < C_DIM; c++)
                    dot = __fmaf_rn(ck[c], xp[(size_t)c * HW], dot);
                float s = __fsub_rn(__fadd_rn(xn_s[px], en_s[k]), __fmul_rn(2.f, dot));
                atomicMin(&beste[px], packkey(s, k));
            }
        }
    }
    __syncthreads();
    if (tid < TNPIX) g_idx[p0 + tid] = (int)(beste[tid] & 0xFFFFFFFFu);
}

// ---------------------------------------------------------------------------
// 3) outputs. gather: 4 channels/thread -> 16B-contiguous codebook reads.
// ---------------------------------------------------------------------------
__global__ void gather_kernel(const float* __restrict__ cb, float* __restrict__ q) {
    long long o4 = (long long)blockIdx.x * blockDim.x + threadIdx.x;
    if (o4 >= (long long)(QN / 4)) return;
    int hw = (int)(o4 & (HW - 1));
    long long t = o4 >> 12;           // b*64 + c4
    int c4 = (int)(t & 63);
    int b  = (int)(t >> 6);
    int k = g_idx[b * HW + hw];
    float4 v = __ldg(reinterpret_cast<const float4*>(cb) + (size_t)k * 64 + c4);
    float* qb = q + ((size_t)b * C_DIM + c4 * 4) * HW + hw;
    qb[0]      = v.x;
    qb[HW]     = v.y;
    qb[2 * HW] = v.z;
    qb[3 * HW] = v.w;
}
__global__ void idxf_kernel(float* __restrict__ out) {
    int n = blockIdx.x * blockDim.x + threadIdx.x;
    if (n < NPIX) out[n] = (float)g_idx[n];
}
__global__ void idxi_kernel(int* __restrict__ out) {
    int n = blockIdx.x * blockDim.x + threadIdx.x;
    if (n < NPIX) out[n] = g_idx[n];
}

// ---------------------------------------------------------------------------
extern "C" void kernel_launch(void* const* d_in, const int* in_sizes, int n_in,
                              void* d_out, int out_size) {
    const float* x  = (const float*)d_in[0];   // (32,256,64,64) f32
    const float* cb = (const float*)d_in[1];   // (1024,256) f32

    cudaFuncSetAttribute(vq_mma_kernel,
                         cudaFuncAttributeMaxDynamicSharedMemorySize, SMEM_TOTAL);

    prep_kernel<<<1540, 256>>>(x, cb);
    vq_mma_kernel<<<NPIX / TNPIX, 256, SMEM_TOTAL>>>(x, cb);

    if (out_size >= NPIX + QN) {
        idxf_kernel<<<NPIX / 256, 256>>>((float*)d_out);
        gather_kernel<<<QN / 4 / 256, 256>>>(cb, (float*)d_out + NPIX);
    } else if (out_size >= QN) {
        gather_kernel<<<QN / 4 / 256, 256>>>(cb, (float*)d_out);
    } else if (out_size >= NPIX) {
        idxi_kernel<<<NPIX / 256, 256>>>((int*)d_out);
    }
}